// round 13
// baseline (speedup 1.0000x reference)
#include <cuda_runtime.h>
#include <cuda_bf16.h>

// Problem: out[r] = prod_{k=0..2} sigmoid((ub[k]-logit(bins[idx[r][k]]))/(ub[k]-lb[k]+1e-4))
// 1024 bins, 3 cols, 16.78M rows -> LUT + streaming gather-product.
//
// R12: as R11 (32KB static single-table REP=8 LUT when lb/ub are identical
// across columns, 3-table REP=2 fallback otherwise; lane-major int4 loads;
// warp-carry row stitching) but the 2-deep software pipeline is removed and
// the kernel is compiled under __launch_bounds__(512, 4): 64 warps/SM instead
// of 48. Latency is covered by occupancy (front-batched LDGs, MLP=3/warp)
// instead of prefetch registers. Templated gather multiplier keeps the fast
// path on compile-time shifts.

#define N_BINS   1024
#define LUT_FLOATS 8192      // 32KB

#define BLOCK_THREADS 512
#define WARPS_PER_BLOCK (BLOCK_THREADS / 32)

// ---------------------------------------------------------------------------
// Warp-carry product stitching round. Lane l of round j holds 4 consecutive
// ints whose columns are (mj, mj+1, mj+2, mj) mod 3. The lane holding a row's
// col-2 element completes the row; leading partials of the next row travel to
// lane+1 via shfl_up, and from lane 31 to lane 0 of the next round.
// ---------------------------------------------------------------------------
template <int MUL>
__device__ __forceinline__ float do_round(int4 v, const float* __restrict__ lut,
                                          int o0, int o1, int o2, int mj,
                                          float qprev, float* __restrict__ out,
                                          unsigned g0, int lane)
{
    float w0 = lut[v.x * MUL + o0];
    float w1 = lut[v.y * MUL + o1];
    float w2 = lut[v.z * MUL + o2];
    float w3 = lut[v.w * MUL + o0];

    float m01 = w0 * w1;
    float w23 = w2 * w3;

    float q = (mj == 0) ? w3 : w23;
    float qin = __shfl_up_sync(0xffffffffu, q, 1);
    if (lane == 0) qin = qprev;

    float res;
    if (mj == 0)      res = m01 * w2;      // full row in-lane
    else if (mj == 1) res = qin * m01;     // qin = col0 from previous lane
    else              res = qin * w0;      // qin = col0*col1 from previous lane

    unsigned rA = g0 / 3u;
    __stcs(&out[rA], res);
    if (mj == 2) __stcs(&out[rA + 1], w1 * w23);  // full row also in-lane

    return __shfl_sync(0xffffffffu, q, 31);
}

template <int MUL>
__device__ __forceinline__ void main_loop(const int4* __restrict__ idx4,
                                          const float* __restrict__ lut,
                                          float* __restrict__ out,
                                          int nchunks, int warpGlobal,
                                          int warpsTotal, int lane,
                                          int offA, int offB, int offC,
                                          int m0, int m1, int m2)
{
    for (int c = warpGlobal; c < nchunks; c += warpsTotal) {
        int4 v0 = __ldcs(idx4 + c * 96 + lane);
        int4 v1 = __ldcs(idx4 + c * 96 + 32 + lane);
        int4 v2 = __ldcs(idx4 + c * 96 + 64 + lane);

        unsigned Gw = (unsigned)c * 384u + 4u * (unsigned)lane;
        float qprev = 0.0f;
        qprev = do_round<MUL>(v0, lut, offA, offB, offC, m0, qprev, out, Gw,        lane);
        qprev = do_round<MUL>(v1, lut, offC, offA, offB, m1, qprev, out, Gw + 128u, lane);
        (void)  do_round<MUL>(v2, lut, offB, offC, offA, m2, qprev, out, Gw + 256u, lane);
    }
}

__device__ __forceinline__ float lut_value(float c, float u, float l) {
    float logit = logf(c / (1.0f - c));
    float x = (u - logit) / (u - l + 1e-4f);
    return 1.0f / (1.0f + expf(-x));
}

__global__ void __launch_bounds__(BLOCK_THREADS, 4)
fused_kernel(const float* __restrict__ bin_centers,
             const int4* __restrict__ idx4,
             const float* __restrict__ lb,
             const float* __restrict__ ub,
             float* __restrict__ out, int nchunks)
{
    __shared__ float lut[LUT_FLOATS];   // 32KB static

    const float l0 = lb[0], l1 = lb[1], l2 = lb[2];
    const float u0 = ub[0], u1 = ub[1], u2 = ub[2];
    const bool eq = (l0 == l1) && (l1 == l2) && (u0 == u1) && (u1 == u2);

    if (eq) {
        // Single table, REP=8: entry i occupies lut[8i .. 8i+7].
        for (int i = threadIdx.x; i < N_BINS; i += BLOCK_THREADS) {
            float v = lut_value(bin_centers[i], u0, l0);
            float4 v4 = make_float4(v, v, v, v);
            float4* dst = (float4*)&lut[i * 8];
            dst[0] = v4;
            dst[1] = v4;
        }
    } else {
        // Three tables, REP=2: table k at float offset k*2048.
        for (int i = threadIdx.x; i < 3 * N_BINS; i += BLOCK_THREADS) {
            int bin = i & (N_BINS - 1);
            int col = i >> 10;
            float u = (col == 0) ? u0 : (col == 1) ? u1 : u2;
            float l = (col == 0) ? l0 : (col == 1) ? l1 : l2;
            float v = lut_value(bin_centers[bin], u, l);
            *(float2*)&lut[i * 2] = make_float2(v, v);
        }
    }
    __syncthreads();

    const int lane = threadIdx.x & 31;
    const int warpsTotal = gridDim.x * WARPS_PER_BLOCK;
    const int warpGlobal = blockIdx.x * WARPS_PER_BLOCK + (threadIdx.x >> 5);

    // Per-lane column rotation: lane's first element has column m = lane%3.
    const int m  = lane % 3;
    const int m0 = m;
    const int m1 = (m + 2) % 3;
    const int m2 = (m + 1) % 3;

    if (eq) {
        int slot = lane & 7;
        main_loop<8>(idx4, lut, out, nchunks, warpGlobal, warpsTotal, lane,
                     slot, slot, slot, m0, m1, m2);
    } else {
        int slot = lane & 1;
        int t0 = slot, t1 = 2048 + slot, t2 = 4096 + slot;
        int offA = (m == 0) ? t0 : (m == 1) ? t1 : t2;
        int offB = (m == 0) ? t1 : (m == 1) ? t2 : t0;
        int offC = (m == 0) ? t2 : (m == 1) ? t0 : t1;
        main_loop<2>(idx4, lut, out, nchunks, warpGlobal, warpsTotal, lane,
                     offA, offB, offC, m0, m1, m2);
    }
}

// ---------------------------------------------------------------------------
// Tail: per-row direct-compute path for rows not covered by full chunks
// (not hit for 16.78M rows; defensive only).
// ---------------------------------------------------------------------------
__global__ void tail_kernel(const float* __restrict__ bin_centers,
                            const int* __restrict__ idx,
                            const float* __restrict__ lb,
                            const float* __restrict__ ub,
                            float* __restrict__ out,
                            int start_row, int n_rows)
{
    int r = start_row + blockIdx.x * blockDim.x + threadIdx.x;
    if (r >= n_rows) return;
    float p = 1.0f;
#pragma unroll
    for (int k = 0; k < 3; k++) {
        float cb = bin_centers[idx[3 * r + k]];
        float logit = logf(cb / (1.0f - cb));
        float x = (ub[k] - logit) / (ub[k] - lb[k] + 1e-4f);
        p *= 1.0f / (1.0f + expf(-x));
    }
    out[r] = p;
}

extern "C" void kernel_launch(void* const* d_in, const int* in_sizes, int n_in,
                              void* d_out, int out_size)
{
    const float* bin_centers = (const float*)d_in[0];
    const int*   idx         = (const int*)d_in[1];
    const float* lb          = (const float*)d_in[2];
    const float* ub          = (const float*)d_in[3];
    float*       out         = (float*)d_out;

    int n_rows = in_sizes[1] / 3;
    int nchunks = n_rows / 128;   // 128 rows per warp-chunk

    if (nchunks > 0) {
        int blocks = 608;         // 4 CTAs/SM x 152 SMs = one wave
        if (blocks * WARPS_PER_BLOCK > nchunks)
            blocks = (nchunks + WARPS_PER_BLOCK - 1) / WARPS_PER_BLOCK;
        fused_kernel<<<blocks, BLOCK_THREADS>>>(
            bin_centers, (const int4*)idx, lb, ub, out, nchunks);
    }

    int done = nchunks * 128;
    if (done < n_rows) {
        int rem = n_rows - done;
        tail_kernel<<<(rem + 255) / 256, 256>>>(
            bin_centers, idx, lb, ub, out, done, n_rows);
    }
}